// round 1
// baseline (speedup 1.0000x reference)
#include <cuda_runtime.h>

#define NB   8
#define HH   64
#define WWD  64
#define LQ   4096                 // 64*64
#define CHN  256
#define NCAT 384                  // 256 (v) + 72 (off) + 36 (msk) padded to 3*128
#define MROWS (NB * LQ)           // 32768

// ---- scratch (device globals; no allocation allowed) ----
__device__ float g_wcat[CHN * NCAT];                 // packed [w_value | w_offset | w_mask | 0]
__device__ float g_bcat[NCAT];
__device__ float g_vom[(size_t)MROWS * NCAT];        // v/off/msk rows, stride 384
__device__ float g_smp[(size_t)MROWS * CHN];         // sampled output, stride 256

// ---------------------------------------------------------------------------
// Pack weights/biases into one padded (256,384) matrix so GEMM-1 is one launch
// ---------------------------------------------------------------------------
__global__ void pack_weights(const float* __restrict__ wv, const float* __restrict__ bv,
                             const float* __restrict__ wo, const float* __restrict__ bo,
                             const float* __restrict__ wm, const float* __restrict__ bm)
{
    int idx = blockIdx.x * blockDim.x + threadIdx.x;
    if (idx < CHN * NCAT) {
        int r = idx / NCAT, c = idx % NCAT;
        float val = 0.f;
        if (c < 256)      val = wv[r * 256 + c];
        else if (c < 328) val = wo[r * 72 + (c - 256)];
        else if (c < 364) val = wm[r * 36 + (c - 328)];
        g_wcat[idx] = val;
    }
    if (idx < NCAT) {
        float val = 0.f;
        if (idx < 256)      val = bv[idx];
        else if (idx < 328) val = bo[idx - 256];
        else if (idx < 364) val = bm[idx - 328];
        g_bcat[idx] = val;
    }
}

// ---------------------------------------------------------------------------
// Classic fp32 SGEMM: C(M,N) = A(M,K) @ B(K,N) + bias(N)
// 128x128 block tile, BK=8, 256 threads, 8x8 per-thread microtile.
// Requires M%128==0, N%128==0, K%8==0 (guaranteed by our sizes).
// ---------------------------------------------------------------------------
__global__ __launch_bounds__(256) void sgemm128(
    const float* __restrict__ A, const float* __restrict__ B,
    const float* __restrict__ bias, float* __restrict__ C,
    int M, int N, int K)
{
    __shared__ float As[8][128];
    __shared__ float Bs[8][128];

    int tid = threadIdx.x;
    int bm = blockIdx.y, bn = blockIdx.x;

    const float* Ab = A + (size_t)bm * 128 * K;
    const float* Bb = B + (size_t)bn * 128;

    int arow = tid >> 1;
    int acol = (tid & 1) * 4;
    int brow = tid >> 5;
    int bcol = (tid & 31) * 4;

    int tx = tid & 15;       // N direction
    int ty = tid >> 4;       // M direction

    float acc[8][8];
#pragma unroll
    for (int i = 0; i < 8; ++i)
#pragma unroll
        for (int j = 0; j < 8; ++j) acc[i][j] = 0.f;

    for (int k0 = 0; k0 < K; k0 += 8) {
        float4 a4 = *(const float4*)(Ab + (size_t)arow * K + k0 + acol);
        As[acol + 0][arow] = a4.x;
        As[acol + 1][arow] = a4.y;
        As[acol + 2][arow] = a4.z;
        As[acol + 3][arow] = a4.w;
        float4 b4 = *(const float4*)(Bb + (size_t)(k0 + brow) * N + bcol);
        *(float4*)(&Bs[brow][bcol]) = b4;
        __syncthreads();

#pragma unroll
        for (int k = 0; k < 8; ++k) {
            float a[8], b[8];
            *(float4*)(&a[0]) = *(const float4*)(&As[k][ty * 8]);
            *(float4*)(&a[4]) = *(const float4*)(&As[k][ty * 8 + 4]);
            *(float4*)(&b[0]) = *(const float4*)(&Bs[k][tx * 8]);
            *(float4*)(&b[4]) = *(const float4*)(&Bs[k][tx * 8 + 4]);
#pragma unroll
            for (int i = 0; i < 8; ++i)
#pragma unroll
                for (int j = 0; j < 8; ++j)
                    acc[i][j] = fmaf(a[i], b[j], acc[i][j]);
        }
        __syncthreads();
    }

#pragma unroll
    for (int i = 0; i < 8; ++i) {
        size_t row = (size_t)bm * 128 + ty * 8 + i;
#pragma unroll
        for (int j = 0; j < 8; j += 4) {
            int col = bn * 128 + tx * 8 + j;
            float4 o;
            o.x = acc[i][j + 0] + bias[col + 0];
            o.y = acc[i][j + 1] + bias[col + 1];
            o.z = acc[i][j + 2] + bias[col + 2];
            o.w = acc[i][j + 3] + bias[col + 3];
            *(float4*)(&C[row * N + col]) = o;
        }
    }
}

// ---------------------------------------------------------------------------
// DCNv4 bilinear sampling.
// One block per query (n, h, w): blockDim = (64 channels, 4 groups).
// Coordinate algebra (derived from reference, simplifies exactly):
//   gx = w + ix - 1 + off_x,  gy = h + iy - 1 + off_y   (unpadded coords)
//   ix = p/3, iy = p%3;  contribution zero outside [0,63] (pad ring is zeros).
// ---------------------------------------------------------------------------
__global__ __launch_bounds__(256) void dcn_sample(const float* __restrict__ vom,
                                                  float* __restrict__ smp)
{
    int q = blockIdx.x;             // 0..32767
    int n = q >> 12;
    int hw = q & 4095;
    int h = hw >> 6, w = hw & 63;
    int c = threadIdx.x;            // 0..63
    int g = threadIdx.y;            // 0..3

    __shared__ float s_off[4][18];
    __shared__ float s_msk[4][9];

    const float* row = vom + (size_t)q * NCAT;
    int t = threadIdx.y * 64 + threadIdx.x;
    if (t < 72)             s_off[t / 18][t % 18] = row[256 + t];
    if (t >= 96 && t < 132) { int u = t - 96; s_msk[u / 9][u % 9] = row[328 + u]; }
    __syncthreads();

    const float* vbase = vom + (size_t)(n * LQ) * NCAT + g * 64 + c;

    float acc = 0.f;
#pragma unroll
    for (int p = 0; p < 9; ++p) {
        int ix = p / 3, iy = p % 3;
        float gx = (float)(w + ix - 1) + s_off[g][p * 2 + 0];
        float gy = (float)(h + iy - 1) + s_off[g][p * 2 + 1];
        float m  = s_msk[g][p];

        float x0f = floorf(gx), y0f = floorf(gy);
        int x0 = (int)x0f, y0 = (int)y0f;
        float wx = gx - x0f, wy = gy - y0f;

        float w00 = (1.f - wx) * (1.f - wy) * m;
        float w10 = wx * (1.f - wy) * m;
        float w01 = (1.f - wx) * wy * m;
        float w11 = wx * wy * m;

        bool vx0 = (x0 >= 0) && (x0 < WWD);
        bool vx1 = (x0 + 1 >= 0) && (x0 + 1 < WWD);

        if (y0 >= 0 && y0 < HH) {
            const float* r0 = vbase + (size_t)(y0 * WWD) * NCAT;
            if (vx0) acc = fmaf(w00, r0[(size_t)x0 * NCAT], acc);
            if (vx1) acc = fmaf(w10, r0[(size_t)(x0 + 1) * NCAT], acc);
        }
        int y1 = y0 + 1;
        if (y1 >= 0 && y1 < HH) {
            const float* r1 = vbase + (size_t)(y1 * WWD) * NCAT;
            if (vx0) acc = fmaf(w01, r1[(size_t)x0 * NCAT], acc);
            if (vx1) acc = fmaf(w11, r1[(size_t)(x0 + 1) * NCAT], acc);
        }
    }

    smp[(size_t)q * CHN + g * 64 + c] = acc;
}

// ---------------------------------------------------------------------------
extern "C" void kernel_launch(void* const* d_in, const int* in_sizes, int n_in,
                              void* d_out, int out_size)
{
    const float* x        = (const float*)d_in[0];
    const float* w_value  = (const float*)d_in[1];
    const float* b_value  = (const float*)d_in[2];
    const float* w_offset = (const float*)d_in[3];
    const float* b_offset = (const float*)d_in[4];
    const float* w_mask   = (const float*)d_in[5];
    const float* b_mask   = (const float*)d_in[6];
    const float* w_out    = (const float*)d_in[7];
    const float* b_out    = (const float*)d_in[8];
    float* out = (float*)d_out;

    float *vom, *smp, *wcat, *bcat;
    cudaGetSymbolAddress((void**)&vom,  g_vom);
    cudaGetSymbolAddress((void**)&smp,  g_smp);
    cudaGetSymbolAddress((void**)&wcat, g_wcat);
    cudaGetSymbolAddress((void**)&bcat, g_bcat);

    pack_weights<<<(CHN * NCAT + 255) / 256, 256>>>(w_value, b_value, w_offset,
                                                    b_offset, w_mask, b_mask);

    // GEMM-1: x(32768,256) @ wcat(256,384) + bcat -> vom
    sgemm128<<<dim3(NCAT / 128, MROWS / 128), 256>>>(x, wcat, bcat, vom,
                                                     MROWS, NCAT, CHN);

    // DCNv4 sampling -> smp(32768,256)
    dcn_sample<<<MROWS, dim3(64, 4)>>>(vom, smp);

    // GEMM-2: smp(32768,256) @ w_out(256,256) + b_out -> out
    sgemm128<<<dim3(CHN / 128, MROWS / 128), 256>>>(smp, w_out, b_out, out,
                                                    MROWS, CHN, CHN);
}

// round 3
// speedup vs baseline: 1.7426x; 1.7426x over previous
#include <cuda_runtime.h>
#include <cstdint>

#define NB   8
#define HH   64
#define WWD  64
#define LQ   4096
#define CHN  256
#define NCAT 384
#define MROWS (NB * LQ)           // 32768
#define KDIM 256
#define PADK 36                   // smem row stride (floats): conflict-free frags

// ---- scratch (device globals; no allocation allowed) ----
__device__ float g_bcat[NCAT];
__device__ float g_vom[(size_t)MROWS * NCAT];
__device__ float g_smp[(size_t)MROWS * CHN];
__device__ float g_bp1[NCAT * KDIM];   // GEMM-1 B, col-major [n][k], tf32-rounded
__device__ float g_bp2[CHN * KDIM];    // GEMM-2 B, col-major [n][k], tf32-rounded

__device__ __forceinline__ float tf32r(float x) {
    asm("cvt.rna.tf32.f32 %0, %0;" : "+f"(x));
    return x;
}

// ---------------------------------------------------------------------------
// Pack: transpose weights to col-major [n][k], tf32-round; concat biases.
// ---------------------------------------------------------------------------
__global__ void pack_weights(const float* __restrict__ wv, const float* __restrict__ bv,
                             const float* __restrict__ wo, const float* __restrict__ bo,
                             const float* __restrict__ wm, const float* __restrict__ bm,
                             const float* __restrict__ wout)
{
    int idx = blockIdx.x * 256 + threadIdx.x;
    if (idx < NCAT * KDIM) {                       // GEMM-1 B
        int n = idx >> 8, k = idx & 255;
        float val = 0.f;
        if (n < 256)      val = wv[k * 256 + n];
        else if (n < 328) val = wo[k * 72 + (n - 256)];
        else if (n < 364) val = wm[k * 36 + (n - 328)];
        g_bp1[idx] = tf32r(val);
    } else if (idx < NCAT * KDIM + CHN * KDIM) {   // GEMM-2 B
        int j = idx - NCAT * KDIM;
        int n = j >> 8, k = j & 255;
        g_bp2[j] = tf32r(wout[k * 256 + n]);
    } else if (idx < NCAT * KDIM + CHN * KDIM + NCAT) {
        int c = idx - (NCAT * KDIM + CHN * KDIM);
        float val = 0.f;
        if (c < 256)      val = bv[c];
        else if (c < 328) val = bo[c - 256];
        else if (c < 364) val = bm[c - 328];
        g_bcat[c] = val;
    }
}

// ---------------------------------------------------------------------------
// tf32 mma.sync GEMM: C(M,N) = A(M,256) @ B^T + bias.
// A row-major (lda=256), B col-major [n][k] (ldb=256).
// CTA tile 128x128, 8 warps (4m x 2n), warp tile 32x64, BK=32.
// ---------------------------------------------------------------------------
__global__ __launch_bounds__(256) void gemm_mma(const float* __restrict__ A,
                                                const float* __restrict__ Bcm,
                                                const float* __restrict__ bias,
                                                float* __restrict__ C, int ldc)
{
    __shared__ float As[128][PADK];
    __shared__ float Bs[128][PADK];

    int tid = threadIdx.x;
    int warp = tid >> 5, lane = tid & 31;
    int wm = warp >> 1;         // 0..3 (M)
    int wn = warp & 1;          // 0..1 (N)
    int gid = lane >> 2, tg = lane & 3;

    const float* Ab = A   + (size_t)blockIdx.y * 128 * KDIM;
    const float* Bb = Bcm + (size_t)blockIdx.x * 128 * KDIM;

    float acc[2][8][4];
#pragma unroll
    for (int mt = 0; mt < 2; ++mt)
#pragma unroll
        for (int nt = 0; nt < 8; ++nt)
#pragma unroll
            for (int i = 0; i < 4; ++i) acc[mt][nt][i] = 0.f;

    for (int k0 = 0; k0 < KDIM; k0 += 32) {
#pragma unroll
        for (int j = 0; j < 4; ++j) {              // A tile: 128 rows x 32 k
            int s = j * 256 + tid;
            int r = s >> 3, q = s & 7;
            float4 v = *(const float4*)(Ab + (size_t)r * KDIM + k0 + q * 4);
            v.x = tf32r(v.x); v.y = tf32r(v.y); v.z = tf32r(v.z); v.w = tf32r(v.w);
            *(float4*)(&As[r][q * 4]) = v;
        }
#pragma unroll
        for (int j = 0; j < 4; ++j) {              // B tile: 128 n x 32 k (pre-rounded)
            int s = j * 256 + tid;
            int r = s >> 3, q = s & 7;
            *(float4*)(&Bs[r][q * 4]) =
                *(const float4*)(Bb + (size_t)r * KDIM + k0 + q * 4);
        }
        __syncthreads();

#pragma unroll
        for (int ks = 0; ks < 4; ++ks) {
            int kb = ks * 8;
            uint32_t a[2][4], b[8][2];
#pragma unroll
            for (int mt = 0; mt < 2; ++mt) {
                int row = wm * 32 + mt * 16;
                a[mt][0] = __float_as_uint(As[row + gid][kb + tg]);
                a[mt][1] = __float_as_uint(As[row + gid + 8][kb + tg]);
                a[mt][2] = __float_as_uint(As[row + gid][kb + tg + 4]);
                a[mt][3] = __float_as_uint(As[row + gid + 8][kb + tg + 4]);
            }
#pragma unroll
            for (int nt = 0; nt < 8; ++nt) {
                int n = wn * 64 + nt * 8 + gid;
                b[nt][0] = __float_as_uint(Bs[n][kb + tg]);
                b[nt][1] = __float_as_uint(Bs[n][kb + tg + 4]);
            }
#pragma unroll
            for (int mt = 0; mt < 2; ++mt)
#pragma unroll
                for (int nt = 0; nt < 8; ++nt) {
                    asm volatile(
                        "mma.sync.aligned.m16n8k8.row.col.f32.tf32.tf32.f32 "
                        "{%0,%1,%2,%3}, {%4,%5,%6,%7}, {%8,%9}, {%0,%1,%2,%3};"
                        : "+f"(acc[mt][nt][0]), "+f"(acc[mt][nt][1]),
                          "+f"(acc[mt][nt][2]), "+f"(acc[mt][nt][3])
                        : "r"(a[mt][0]), "r"(a[mt][1]), "r"(a[mt][2]), "r"(a[mt][3]),
                          "r"(b[nt][0]), "r"(b[nt][1]));
                }
        }
        __syncthreads();
    }

    // epilogue: c0,c1 -> (row gid, cols 2tg,2tg+1); c2,c3 -> row gid+8
#pragma unroll
    for (int mt = 0; mt < 2; ++mt) {
#pragma unroll
        for (int i = 0; i < 2; ++i) {
            size_t row = (size_t)blockIdx.y * 128 + wm * 32 + mt * 16 + gid + i * 8;
            float* Crow = C + row * (size_t)ldc;
#pragma unroll
            for (int nt = 0; nt < 8; ++nt) {
                int col = blockIdx.x * 128 + wn * 64 + nt * 8 + 2 * tg;
                float2 o;
                o.x = acc[mt][nt][2 * i + 0] + bias[col + 0];
                o.y = acc[mt][nt][2 * i + 1] + bias[col + 1];
                *(float2*)(&Crow[col]) = o;
            }
        }
    }
}

// ---------------------------------------------------------------------------
// DCNv4 bilinear sampling (unchanged; proven correct).
//   gx = w + ix - 1 + off_x,  gy = h + iy - 1 + off_y  (ix=p/3, iy=p%3)
// ---------------------------------------------------------------------------
__global__ __launch_bounds__(256) void dcn_sample(const float* __restrict__ vom,
                                                  float* __restrict__ smp)
{
    int q = blockIdx.x;
    int n = q >> 12;
    int hw = q & 4095;
    int h = hw >> 6, w = hw & 63;
    int c = threadIdx.x;
    int g = threadIdx.y;

    __shared__ float s_off[4][18];
    __shared__ float s_msk[4][9];

    const float* row = vom + (size_t)q * NCAT;
    int t = threadIdx.y * 64 + threadIdx.x;
    if (t < 72)             s_off[t / 18][t % 18] = row[256 + t];
    if (t >= 96 && t < 132) { int u = t - 96; s_msk[u / 9][u % 9] = row[328 + u]; }
    __syncthreads();

    const float* vbase = vom + (size_t)(n * LQ) * NCAT + g * 64 + c;

    float acc = 0.f;
#pragma unroll
    for (int p = 0; p < 9; ++p) {
        int ix = p / 3, iy = p % 3;
        float gx = (float)(w + ix - 1) + s_off[g][p * 2 + 0];
        float gy = (float)(h + iy - 1) + s_off[g][p * 2 + 1];
        float m  = s_msk[g][p];

        float x0f = floorf(gx), y0f = floorf(gy);
        int x0 = (int)x0f, y0 = (int)y0f;
        float wx = gx - x0f, wy = gy - y0f;

        float w00 = (1.f - wx) * (1.f - wy) * m;
        float w10 = wx * (1.f - wy) * m;
        float w01 = (1.f - wx) * wy * m;
        float w11 = wx * wy * m;

        bool vx0 = (x0 >= 0) && (x0 < WWD);
        bool vx1 = (x0 + 1 >= 0) && (x0 + 1 < WWD);

        if (y0 >= 0 && y0 < HH) {
            const float* r0 = vbase + (size_t)(y0 * WWD) * NCAT;
            if (vx0) acc = fmaf(w00, r0[(size_t)x0 * NCAT], acc);
            if (vx1) acc = fmaf(w10, r0[(size_t)(x0 + 1) * NCAT], acc);
        }
        int y1 = y0 + 1;
        if (y1 >= 0 && y1 < HH) {
            const float* r1 = vbase + (size_t)(y1 * WWD) * NCAT;
            if (vx0) acc = fmaf(w01, r1[(size_t)x0 * NCAT], acc);
            if (vx1) acc = fmaf(w11, r1[(size_t)(x0 + 1) * NCAT], acc);
        }
    }

    smp[(size_t)q * CHN + g * 64 + c] = acc;
}

// ---------------------------------------------------------------------------
extern "C" void kernel_launch(void* const* d_in, const int* in_sizes, int n_in,
                              void* d_out, int out_size)
{
    const float* x        = (const float*)d_in[0];
    const float* w_value  = (const float*)d_in[1];
    const float* b_value  = (const float*)d_in[2];
    const float* w_offset = (const float*)d_in[3];
    const float* b_offset = (const float*)d_in[4];
    const float* w_mask   = (const float*)d_in[5];
    const float* b_mask   = (const float*)d_in[6];
    const float* w_out    = (const float*)d_in[7];
    const float* b_out    = (const float*)d_in[8];
    float* out = (float*)d_out;

    float *vom, *smp, *bcat, *bp1, *bp2;
    cudaGetSymbolAddress((void**)&vom,  g_vom);
    cudaGetSymbolAddress((void**)&smp,  g_smp);
    cudaGetSymbolAddress((void**)&bcat, g_bcat);
    cudaGetSymbolAddress((void**)&bp1,  g_bp1);
    cudaGetSymbolAddress((void**)&bp2,  g_bp2);

    int pack_elems = NCAT * KDIM + CHN * KDIM + NCAT;
    pack_weights<<<(pack_elems + 255) / 256, 256>>>(w_value, b_value, w_offset,
                                                    b_offset, w_mask, b_mask, w_out);

    // GEMM-1: x(32768,256) @ [wv|wo|wm](256,384) + bcat -> vom (ldc=384)
    gemm_mma<<<dim3(NCAT / 128, MROWS / 128), 256>>>(x, bp1, bcat, vom, NCAT);

    // DCNv4 sampling -> smp(32768,256)
    dcn_sample<<<MROWS, dim3(64, 4)>>>(vom, smp);

    // GEMM-2: smp(32768,256) @ w_out(256,256) + b_out -> out (ldc=256)
    gemm_mma<<<dim3(CHN / 128, MROWS / 128), 256>>>(smp, bp2, b_out, out, CHN);
}

// round 4
// speedup vs baseline: 2.7469x; 1.5763x over previous
#include <cuda_runtime.h>
#include <cstdint>

#define NB   8
#define HH   64
#define WWD  64
#define LQ   4096
#define CHN  256
#define NCAT 384
#define MROWS (NB * LQ)           // 32768
#define KDIM 256
#define PADK 36                   // smem row stride (floats)
#define BUF_F (128 * PADK)        // 4608 floats per tile buffer
#define GEMM_SMEM_BYTES (4 * BUF_F * 4)   // A0,A1,B0,B1 = 73728 B

// ---- scratch (device globals; no allocation allowed) ----
__device__ float g_bcat[NCAT];
__device__ float g_xr[(size_t)MROWS * KDIM];    // tf32-rounded x
__device__ float g_vom[(size_t)MROWS * NCAT];
__device__ float g_smp[(size_t)MROWS * CHN];
__device__ float g_bp1[NCAT * KDIM];   // GEMM-1 B, col-major [n][k], tf32-rounded
__device__ float g_bp2[CHN * KDIM];    // GEMM-2 B, col-major [n][k], tf32-rounded

__device__ __forceinline__ float tf32r(float x) {
    asm("cvt.rna.tf32.f32 %0, %0;" : "+f"(x));
    return x;
}
__device__ __forceinline__ void cpasync16(uint32_t dst, const float* src) {
    asm volatile("cp.async.ca.shared.global [%0], [%1], 16;"
                 :: "r"(dst), "l"(src));
}

// ---------------------------------------------------------------------------
// Pack weights (col-major, tf32-rounded) + concat biases.
// ---------------------------------------------------------------------------
__global__ void pack_weights(const float* __restrict__ wv, const float* __restrict__ bv,
                             const float* __restrict__ wo, const float* __restrict__ bo,
                             const float* __restrict__ wm, const float* __restrict__ bm,
                             const float* __restrict__ wout)
{
    int idx = blockIdx.x * 256 + threadIdx.x;
    if (idx < NCAT * KDIM) {
        int n = idx >> 8, k = idx & 255;
        float val = 0.f;
        if (n < 256)      val = wv[k * 256 + n];
        else if (n < 328) val = wo[k * 72 + (n - 256)];
        else if (n < 364) val = wm[k * 36 + (n - 328)];
        g_bp1[idx] = tf32r(val);
    } else if (idx < NCAT * KDIM + CHN * KDIM) {
        int j = idx - NCAT * KDIM;
        int n = j >> 8, k = j & 255;
        g_bp2[j] = tf32r(wout[k * 256 + n]);
    } else if (idx < NCAT * KDIM + CHN * KDIM + NCAT) {
        int c = idx - (NCAT * KDIM + CHN * KDIM);
        float val = 0.f;
        if (c < 256)      val = bv[c];
        else if (c < 328) val = bo[c - 256];
        else if (c < 364) val = bm[c - 328];
        g_bcat[c] = val;
    }
}

// ---------------------------------------------------------------------------
// tf32-round x (streaming, float4). Exactly MROWS*KDIM/4 threads.
// ---------------------------------------------------------------------------
__global__ __launch_bounds__(256) void round_x(const float* __restrict__ x,
                                               float* __restrict__ xr)
{
    size_t i = ((size_t)blockIdx.x * 256 + threadIdx.x) * 4;
    float4 v = *(const float4*)(x + i);
    v.x = tf32r(v.x); v.y = tf32r(v.y); v.z = tf32r(v.z); v.w = tf32r(v.w);
    *(float4*)(xr + i) = v;
}

// ---------------------------------------------------------------------------
// tf32 mma.sync GEMM, cp.async double-buffered.
// C(M,N) = A(M,256) @ B^T + bias. A row-major pre-tf32-rounded; B col-major.
// CTA tile 128x128, 8 warps (4m x 2n), warp tile 32x64, BK=32.
// ---------------------------------------------------------------------------
__global__ __launch_bounds__(256) void gemm_mma(const float* __restrict__ A,
                                                const float* __restrict__ Bcm,
                                                const float* __restrict__ bias,
                                                float* __restrict__ C, int ldc)
{
    extern __shared__ float smem[];
    // layout: A0 @0, A1 @BUF_F, B0 @2*BUF_F, B1 @3*BUF_F
    uint32_t sbase = (uint32_t)__cvta_generic_to_shared(smem);

    int tid = threadIdx.x;
    int warp = tid >> 5, lane = tid & 31;
    int wmi = warp >> 1;
    int wni = warp & 1;
    int gid = lane >> 2, tg = lane & 3;

    const float* Ab = A   + (size_t)blockIdx.y * 128 * KDIM;
    const float* Bb = Bcm + (size_t)blockIdx.x * 128 * KDIM;

    // per-thread tile slot: 4 float4 per tile, slot s covers row r=s>>3, quad q=s&7
    int r0 = tid >> 3, q0 = (tid & 7) * 4;   // j=0 slot (stride 256 slots -> +32 rows)

    float acc[2][8][4];
#pragma unroll
    for (int mt = 0; mt < 2; ++mt)
#pragma unroll
        for (int nt = 0; nt < 8; ++nt)
#pragma unroll
            for (int i = 0; i < 4; ++i) acc[mt][nt][i] = 0.f;

    auto issue = [&](int c, int b) {
        uint32_t adst = sbase + (uint32_t)(b * BUF_F) * 4;
        uint32_t bdst = sbase + (uint32_t)((2 + b) * BUF_F) * 4;
        const float* asrc = Ab + c * 32;
        const float* bsrc = Bb + c * 32;
#pragma unroll
        for (int j = 0; j < 4; ++j) {
            int r = r0 + j * 32;
            cpasync16(adst + (uint32_t)(r * PADK + q0) * 4, asrc + (size_t)r * KDIM + q0);
        }
#pragma unroll
        for (int j = 0; j < 4; ++j) {
            int r = r0 + j * 32;
            cpasync16(bdst + (uint32_t)(r * PADK + q0) * 4, bsrc + (size_t)r * KDIM + q0);
        }
        asm volatile("cp.async.commit_group;" ::: "memory");
    };

    issue(0, 0);

    for (int c = 0; c < 8; ++c) {
        int b = c & 1;
        if (c < 7) {
            issue(c + 1, b ^ 1);
            asm volatile("cp.async.wait_group 1;" ::: "memory");
        } else {
            asm volatile("cp.async.wait_group 0;" ::: "memory");
        }
        __syncthreads();

        const float* As = smem + b * BUF_F;
        const float* Bs = smem + (2 + b) * BUF_F;
#pragma unroll
        for (int ks = 0; ks < 4; ++ks) {
            int kb = ks * 8;
            uint32_t a[2][4], bf[8][2];
#pragma unroll
            for (int mt = 0; mt < 2; ++mt) {
                int row = wmi * 32 + mt * 16;
                a[mt][0] = __float_as_uint(As[(row + gid) * PADK + kb + tg]);
                a[mt][1] = __float_as_uint(As[(row + gid + 8) * PADK + kb + tg]);
                a[mt][2] = __float_as_uint(As[(row + gid) * PADK + kb + tg + 4]);
                a[mt][3] = __float_as_uint(As[(row + gid + 8) * PADK + kb + tg + 4]);
            }
#pragma unroll
            for (int nt = 0; nt < 8; ++nt) {
                int n = wni * 64 + nt * 8 + gid;
                bf[nt][0] = __float_as_uint(Bs[n * PADK + kb + tg]);
                bf[nt][1] = __float_as_uint(Bs[n * PADK + kb + tg + 4]);
            }
#pragma unroll
            for (int mt = 0; mt < 2; ++mt)
#pragma unroll
                for (int nt = 0; nt < 8; ++nt) {
                    asm volatile(
                        "mma.sync.aligned.m16n8k8.row.col.f32.tf32.tf32.f32 "
                        "{%0,%1,%2,%3}, {%4,%5,%6,%7}, {%8,%9}, {%0,%1,%2,%3};"
                        : "+f"(acc[mt][nt][0]), "+f"(acc[mt][nt][1]),
                          "+f"(acc[mt][nt][2]), "+f"(acc[mt][nt][3])
                        : "r"(a[mt][0]), "r"(a[mt][1]), "r"(a[mt][2]), "r"(a[mt][3]),
                          "r"(bf[nt][0]), "r"(bf[nt][1]));
                }
        }
        __syncthreads();
    }

#pragma unroll
    for (int mt = 0; mt < 2; ++mt) {
#pragma unroll
        for (int i = 0; i < 2; ++i) {
            size_t row = (size_t)blockIdx.y * 128 + wmi * 32 + mt * 16 + gid + i * 8;
            float* Crow = C + row * (size_t)ldc;
#pragma unroll
            for (int nt = 0; nt < 8; ++nt) {
                int col = blockIdx.x * 128 + wni * 64 + nt * 8 + 2 * tg;
                float2 o;
                o.x = acc[mt][nt][2 * i + 0] + bias[col + 0];
                o.y = acc[mt][nt][2 * i + 1] + bias[col + 1];
                *(float2*)(&Crow[col]) = o;
            }
        }
    }
}

// ---------------------------------------------------------------------------
// DCNv4 bilinear sampling, float4 channels. 4 queries per 256-thread block.
//   gx = w + ix - 1 + off_x,  gy = h + iy - 1 + off_y  (ix=p/3, iy=p%3)
// Output stored tf32-rounded (GEMM-2 consumes it via cp.async).
// ---------------------------------------------------------------------------
__global__ __launch_bounds__(256) void dcn_sample(const float* __restrict__ vom,
                                                  float* __restrict__ smp)
{
    int tid = threadIdx.x;
    int qi = tid >> 6;          // 0..3 query within block
    int s  = tid & 63;
    int g  = s >> 4;            // group 0..3
    int c4 = s & 15;            // float4 slot within group
    int qbase = blockIdx.x * 4;

    __shared__ float s_off[4][4][18];
    __shared__ float s_msk[4][4][9];

    for (int t = tid; t < 432; t += 256) {
        int qq = t / 108, u = t % 108;
        const float* row = vom + (size_t)(qbase + qq) * NCAT;
        if (u < 72) s_off[qq][u / 18][u % 18] = row[256 + u];
        else { int v = u - 72; s_msk[qq][v / 9][v % 9] = row[328 + v]; }
    }
    __syncthreads();

    int q = qbase + qi;
    int n = q >> 12, hw = q & 4095, h = hw >> 6, w = hw & 63;
    const float* vbase = vom + (size_t)(n * LQ) * NCAT + g * 64 + c4 * 4;

    float4 acc = make_float4(0.f, 0.f, 0.f, 0.f);
#pragma unroll
    for (int p = 0; p < 9; ++p) {
        int ix = p / 3, iy = p % 3;
        float gx = (float)(w + ix - 1) + s_off[qi][g][p * 2 + 0];
        float gy = (float)(h + iy - 1) + s_off[qi][g][p * 2 + 1];
        float m  = s_msk[qi][g][p];

        float x0f = floorf(gx), y0f = floorf(gy);
        int x0 = (int)x0f, y0 = (int)y0f;
        float wx = gx - x0f, wy = gy - y0f;

        float w00 = (1.f - wx) * (1.f - wy) * m;
        float w10 = wx * (1.f - wy) * m;
        float w01 = (1.f - wx) * wy * m;
        float w11 = wx * wy * m;

        bool vx0 = (x0 >= 0) && (x0 < WWD);
        bool vx1 = (x0 + 1 >= 0) && (x0 + 1 < WWD);

        if (y0 >= 0 && y0 < HH) {
            const float* r0 = vbase + (size_t)(y0 * WWD) * NCAT;
            if (vx0) {
                float4 v = *(const float4*)(r0 + (size_t)x0 * NCAT);
                acc.x = fmaf(w00, v.x, acc.x); acc.y = fmaf(w00, v.y, acc.y);
                acc.z = fmaf(w00, v.z, acc.z); acc.w = fmaf(w00, v.w, acc.w);
            }
            if (vx1) {
                float4 v = *(const float4*)(r0 + (size_t)(x0 + 1) * NCAT);
                acc.x = fmaf(w10, v.x, acc.x); acc.y = fmaf(w10, v.y, acc.y);
                acc.z = fmaf(w10, v.z, acc.z); acc.w = fmaf(w10, v.w, acc.w);
            }
        }
        int y1 = y0 + 1;
        if (y1 >= 0 && y1 < HH) {
            const float* r1 = vbase + (size_t)(y1 * WWD) * NCAT;
            if (vx0) {
                float4 v = *(const float4*)(r1 + (size_t)x0 * NCAT);
                acc.x = fmaf(w01, v.x, acc.x); acc.y = fmaf(w01, v.y, acc.y);
                acc.z = fmaf(w01, v.z, acc.z); acc.w = fmaf(w01, v.w, acc.w);
            }
            if (vx1) {
                float4 v = *(const float4*)(r1 + (size_t)(x0 + 1) * NCAT);
                acc.x = fmaf(w11, v.x, acc.x); acc.y = fmaf(w11, v.y, acc.y);
                acc.z = fmaf(w11, v.z, acc.z); acc.w = fmaf(w11, v.w, acc.w);
            }
        }
    }

    acc.x = tf32r(acc.x); acc.y = tf32r(acc.y);
    acc.z = tf32r(acc.z); acc.w = tf32r(acc.w);
    *(float4*)(smp + (size_t)q * CHN + g * 64 + c4 * 4) = acc;
}

// ---------------------------------------------------------------------------
extern "C" void kernel_launch(void* const* d_in, const int* in_sizes, int n_in,
                              void* d_out, int out_size)
{
    const float* x        = (const float*)d_in[0];
    const float* w_value  = (const float*)d_in[1];
    const float* b_value  = (const float*)d_in[2];
    const float* w_offset = (const float*)d_in[3];
    const float* b_offset = (const float*)d_in[4];
    const float* w_mask   = (const float*)d_in[5];
    const float* b_mask   = (const float*)d_in[6];
    const float* w_out    = (const float*)d_in[7];
    const float* b_out    = (const float*)d_in[8];
    float* out = (float*)d_out;

    float *xr, *vom, *smp, *bcat, *bp1, *bp2;
    cudaGetSymbolAddress((void**)&xr,   g_xr);
    cudaGetSymbolAddress((void**)&vom,  g_vom);
    cudaGetSymbolAddress((void**)&smp,  g_smp);
    cudaGetSymbolAddress((void**)&bcat, g_bcat);
    cudaGetSymbolAddress((void**)&bp1,  g_bp1);
    cudaGetSymbolAddress((void**)&bp2,  g_bp2);

    cudaFuncSetAttribute(gemm_mma, cudaFuncAttributeMaxDynamicSharedMemorySize,
                         GEMM_SMEM_BYTES);

    int pack_elems = NCAT * KDIM + CHN * KDIM + NCAT;
    pack_weights<<<(pack_elems + 255) / 256, 256>>>(w_value, b_value, w_offset,
                                                    b_offset, w_mask, b_mask, w_out);

    round_x<<<(MROWS * KDIM / 4) / 256, 256>>>(x, xr);

    // GEMM-1: xr(32768,256) @ [wv|wo|wm](256,384) + bcat -> vom (ldc=384)
    gemm_mma<<<dim3(NCAT / 128, MROWS / 128), 256, GEMM_SMEM_BYTES>>>(xr, bp1, bcat,
                                                                      vom, NCAT);

    // DCNv4 sampling -> smp(32768,256), tf32-rounded
    dcn_sample<<<MROWS / 4, 256>>>(vom, smp);

    // GEMM-2: smp(32768,256) @ w_out(256,256) + b_out -> out (ldc=256)
    gemm_mma<<<dim3(CHN / 128, MROWS / 128), 256, GEMM_SMEM_BYTES>>>(smp, bp2, b_out,
                                                                     out, CHN);
}

// round 5
// speedup vs baseline: 3.1311x; 1.1399x over previous
#include <cuda_runtime.h>
#include <cstdint>

#define NB   8
#define HH   64
#define WWD  64
#define LQ   4096
#define CHN  256
#define NCAT 384
#define MROWS (NB * LQ)           // 32768
#define KDIM 256
#define PADK 36                   // smem row stride (floats)
#define BUF_F (128 * PADK)        // 4608 floats per tile buffer
#define GEMM_SMEM_BYTES (4 * BUF_F * 4)   // A0,A1,B0,B1 = 73728 B

// ---- scratch (device globals; no allocation allowed) ----
__device__ float g_bcat[NCAT];
__device__ float g_vom[(size_t)MROWS * NCAT];
__device__ float g_smp[(size_t)MROWS * CHN];
__device__ float g_bp1[NCAT * KDIM];   // GEMM-1 B, col-major [n][k], tf32-rounded
__device__ float g_bp2[CHN * KDIM];    // GEMM-2 B, col-major [n][k], tf32-rounded

__device__ __forceinline__ float tf32r(float x) {
    asm("cvt.rna.tf32.f32 %0, %0;" : "+f"(x));
    return x;
}
__device__ __forceinline__ void cpasync16(uint32_t dst, const float* src) {
    asm volatile("cp.async.ca.shared.global [%0], [%1], 16;"
                 :: "r"(dst), "l"(src));
}

// ---------------------------------------------------------------------------
// Pack weights (col-major, tf32-rounded) + concat biases.
// ---------------------------------------------------------------------------
__global__ void pack_weights(const float* __restrict__ wv, const float* __restrict__ bv,
                             const float* __restrict__ wo, const float* __restrict__ bo,
                             const float* __restrict__ wm, const float* __restrict__ bm,
                             const float* __restrict__ wout)
{
    int idx = blockIdx.x * 256 + threadIdx.x;
    if (idx < NCAT * KDIM) {
        int n = idx >> 8, k = idx & 255;
        float val = 0.f;
        if (n < 256)      val = wv[k * 256 + n];
        else if (n < 328) val = wo[k * 72 + (n - 256)];
        else if (n < 364) val = wm[k * 36 + (n - 328)];
        g_bp1[idx] = tf32r(val);
    } else if (idx < NCAT * KDIM + CHN * KDIM) {
        int j = idx - NCAT * KDIM;
        int n = j >> 8, k = j & 255;
        g_bp2[j] = tf32r(wout[k * 256 + n]);
    } else if (idx < NCAT * KDIM + CHN * KDIM + NCAT) {
        int c = idx - (NCAT * KDIM + CHN * KDIM);
        float val = 0.f;
        if (c < 256)      val = bv[c];
        else if (c < 328) val = bo[c - 256];
        else if (c < 364) val = bm[c - 328];
        g_bcat[c] = val;
    }
}

// ---------------------------------------------------------------------------
// tf32 mma.sync GEMM, cp.async double-buffered.
// C(M,N) = A(M,256) @ B^T + bias. B col-major pre-rounded.
// ROUND_A=1: apply tf32 rounding to A fragments after LDS (raw fp32 A input).
// CTA tile 128x128, 8 warps (4m x 2n), warp tile 32x64, BK=32.
// ---------------------------------------------------------------------------
template<int ROUND_A>
__global__ __launch_bounds__(256) void gemm_mma(const float* __restrict__ A,
                                                const float* __restrict__ Bcm,
                                                const float* __restrict__ bias,
                                                float* __restrict__ C, int ldc)
{
    extern __shared__ float smem[];
    uint32_t sbase = (uint32_t)__cvta_generic_to_shared(smem);

    int tid = threadIdx.x;
    int warp = tid >> 5, lane = tid & 31;
    int wmi = warp >> 1;
    int wni = warp & 1;
    int gid = lane >> 2, tg = lane & 3;

    const float* Ab = A   + (size_t)blockIdx.y * 128 * KDIM;
    const float* Bb = Bcm + (size_t)blockIdx.x * 128 * KDIM;

    int r0 = tid >> 3, q0 = (tid & 7) * 4;

    float acc[2][8][4];
#pragma unroll
    for (int mt = 0; mt < 2; ++mt)
#pragma unroll
        for (int nt = 0; nt < 8; ++nt)
#pragma unroll
            for (int i = 0; i < 4; ++i) acc[mt][nt][i] = 0.f;

    auto issue = [&](int c, int b) {
        uint32_t adst = sbase + (uint32_t)(b * BUF_F) * 4;
        uint32_t bdst = sbase + (uint32_t)((2 + b) * BUF_F) * 4;
        const float* asrc = Ab + c * 32;
        const float* bsrc = Bb + c * 32;
#pragma unroll
        for (int j = 0; j < 4; ++j) {
            int r = r0 + j * 32;
            cpasync16(adst + (uint32_t)(r * PADK + q0) * 4, asrc + (size_t)r * KDIM + q0);
        }
#pragma unroll
        for (int j = 0; j < 4; ++j) {
            int r = r0 + j * 32;
            cpasync16(bdst + (uint32_t)(r * PADK + q0) * 4, bsrc + (size_t)r * KDIM + q0);
        }
        asm volatile("cp.async.commit_group;" ::: "memory");
    };

    issue(0, 0);

    for (int c = 0; c < 8; ++c) {
        int b = c & 1;
        if (c < 7) {
            issue(c + 1, b ^ 1);
            asm volatile("cp.async.wait_group 1;" ::: "memory");
        } else {
            asm volatile("cp.async.wait_group 0;" ::: "memory");
        }
        __syncthreads();

        const float* As = smem + b * BUF_F;
        const float* Bs = smem + (2 + b) * BUF_F;
#pragma unroll
        for (int ks = 0; ks < 4; ++ks) {
            int kb = ks * 8;
            uint32_t a[2][4], bf[8][2];
#pragma unroll
            for (int mt = 0; mt < 2; ++mt) {
                int row = wmi * 32 + mt * 16;
                float a0 = As[(row + gid) * PADK + kb + tg];
                float a1 = As[(row + gid + 8) * PADK + kb + tg];
                float a2 = As[(row + gid) * PADK + kb + tg + 4];
                float a3 = As[(row + gid + 8) * PADK + kb + tg + 4];
                if (ROUND_A) { a0 = tf32r(a0); a1 = tf32r(a1); a2 = tf32r(a2); a3 = tf32r(a3); }
                a[mt][0] = __float_as_uint(a0);
                a[mt][1] = __float_as_uint(a1);
                a[mt][2] = __float_as_uint(a2);
                a[mt][3] = __float_as_uint(a3);
            }
#pragma unroll
            for (int nt = 0; nt < 8; ++nt) {
                int n = wni * 64 + nt * 8 + gid;
                bf[nt][0] = __float_as_uint(Bs[n * PADK + kb + tg]);
                bf[nt][1] = __float_as_uint(Bs[n * PADK + kb + tg + 4]);
            }
#pragma unroll
            for (int mt = 0; mt < 2; ++mt)
#pragma unroll
                for (int nt = 0; nt < 8; ++nt) {
                    asm volatile(
                        "mma.sync.aligned.m16n8k8.row.col.f32.tf32.tf32.f32 "
                        "{%0,%1,%2,%3}, {%4,%5,%6,%7}, {%8,%9}, {%0,%1,%2,%3};"
                        : "+f"(acc[mt][nt][0]), "+f"(acc[mt][nt][1]),
                          "+f"(acc[mt][nt][2]), "+f"(acc[mt][nt][3])
                        : "r"(a[mt][0]), "r"(a[mt][1]), "r"(a[mt][2]), "r"(a[mt][3]),
                          "r"(bf[nt][0]), "r"(bf[nt][1]));
                }
        }
        __syncthreads();
    }

#pragma unroll
    for (int mt = 0; mt < 2; ++mt) {
#pragma unroll
        for (int i = 0; i < 2; ++i) {
            size_t row = (size_t)blockIdx.y * 128 + wmi * 32 + mt * 16 + gid + i * 8;
            float* Crow = C + row * (size_t)ldc;
#pragma unroll
            for (int nt = 0; nt < 8; ++nt) {
                int col = blockIdx.x * 128 + wni * 64 + nt * 8 + 2 * tg;
                float2 o;
                o.x = acc[mt][nt][2 * i + 0] + bias[col + 0];
                o.y = acc[mt][nt][2 * i + 1] + bias[col + 1];
                *(float2*)(&Crow[col]) = o;
            }
        }
    }
}

// ---------------------------------------------------------------------------
// DCNv4 bilinear sampling. 4 queries per 256-thread block.
// Stage 1 (144 threads): per (q,g,p) compute 4 bilinear weights (mask and
// out-of-bounds validity folded in; invalid corner -> weight 0, coord clamped)
// and 4 pre-scaled byte offsets into the group's value plane.
// Stage 2 (all 256): branchless gathers: 4x LDG.128 + 16 FFMA per point.
// ---------------------------------------------------------------------------
__global__ __launch_bounds__(256) void dcn_sample(const float* __restrict__ vom,
                                                  float* __restrict__ smp)
{
    int tid = threadIdx.x;
    int qbase = blockIdx.x * 4;

    __shared__ float4 s_wgt[4][4][9];
    __shared__ int4   s_idx[4][4][9];

    if (tid < 144) {
        int qq = tid / 36, u = tid % 36;
        int g = u / 9, p = u % 9;
        int q = qbase + qq;
        int hw = q & 4095, h = hw >> 6, w = hw & 63;
        const float* row = vom + (size_t)q * NCAT;
        float ox = row[256 + g * 18 + p * 2];
        float oy = row[256 + g * 18 + p * 2 + 1];
        float m  = row[328 + g * 9 + p];

        int ix = p / 3, iy = p % 3;
        float gx = (float)(w + ix - 1) + ox;
        float gy = (float)(h + iy - 1) + oy;

        float x0f = floorf(gx), y0f = floorf(gy);
        int x0 = (int)x0f, y0 = (int)y0f;
        float wx = gx - x0f, wy = gy - y0f;

        float vx0 = (x0 >= 0 && x0 < WWD) ? 1.f : 0.f;
        float vx1 = (x0 + 1 >= 0 && x0 + 1 < WWD) ? 1.f : 0.f;
        float vy0 = (y0 >= 0 && y0 < HH) ? 1.f : 0.f;
        float vy1 = (y0 + 1 >= 0 && y0 + 1 < HH) ? 1.f : 0.f;

        float4 W;
        W.x = (1.f - wx) * (1.f - wy) * m * vx0 * vy0;
        W.y = wx * (1.f - wy) * m * vx1 * vy0;
        W.z = (1.f - wx) * wy * m * vx0 * vy1;
        W.w = wx * wy * m * vx1 * vy1;

        int x0c = min(max(x0, 0), WWD - 1);
        int x1c = min(max(x0 + 1, 0), WWD - 1);
        int y0c = min(max(y0, 0), HH - 1);
        int y1c = min(max(y0 + 1, 0), HH - 1);

        int4 O;
        O.x = (y0c * WWD + x0c) * (NCAT * 4);
        O.y = (y0c * WWD + x1c) * (NCAT * 4);
        O.z = (y1c * WWD + x0c) * (NCAT * 4);
        O.w = (y1c * WWD + x1c) * (NCAT * 4);

        s_wgt[qq][g][p] = W;
        s_idx[qq][g][p] = O;
    }
    __syncthreads();

    int qi = tid >> 6;
    int s  = tid & 63;
    int g  = s >> 4;
    int c4 = s & 15;
    int q = qbase + qi;
    int n = q >> 12;

    const char* vb = (const char*)(vom + (size_t)(n * LQ) * NCAT + g * 64 + c4 * 4);

    float4 acc = make_float4(0.f, 0.f, 0.f, 0.f);
#pragma unroll
    for (int p = 0; p < 9; ++p) {
        float4 W = s_wgt[qi][g][p];
        int4   O = s_idx[qi][g][p];

        float4 v00 = *(const float4*)(vb + O.x);
        float4 v10 = *(const float4*)(vb + O.y);
        float4 v01 = *(const float4*)(vb + O.z);
        float4 v11 = *(const float4*)(vb + O.w);

        acc.x = fmaf(W.x, v00.x, acc.x); acc.y = fmaf(W.x, v00.y, acc.y);
        acc.z = fmaf(W.x, v00.z, acc.z); acc.w = fmaf(W.x, v00.w, acc.w);
        acc.x = fmaf(W.y, v10.x, acc.x); acc.y = fmaf(W.y, v10.y, acc.y);
        acc.z = fmaf(W.y, v10.z, acc.z); acc.w = fmaf(W.y, v10.w, acc.w);
        acc.x = fmaf(W.z, v01.x, acc.x); acc.y = fmaf(W.z, v01.y, acc.y);
        acc.z = fmaf(W.z, v01.z, acc.z); acc.w = fmaf(W.z, v01.w, acc.w);
        acc.x = fmaf(W.w, v11.x, acc.x); acc.y = fmaf(W.w, v11.y, acc.y);
        acc.z = fmaf(W.w, v11.z, acc.z); acc.w = fmaf(W.w, v11.w, acc.w);
    }

    acc.x = tf32r(acc.x); acc.y = tf32r(acc.y);
    acc.z = tf32r(acc.z); acc.w = tf32r(acc.w);
    *(float4*)(smp + (size_t)q * CHN + g * 64 + c4 * 4) = acc;
}

// ---------------------------------------------------------------------------
extern "C" void kernel_launch(void* const* d_in, const int* in_sizes, int n_in,
                              void* d_out, int out_size)
{
    const float* x        = (const float*)d_in[0];
    const float* w_value  = (const float*)d_in[1];
    const float* b_value  = (const float*)d_in[2];
    const float* w_offset = (const float*)d_in[3];
    const float* b_offset = (const float*)d_in[4];
    const float* w_mask   = (const float*)d_in[5];
    const float* b_mask   = (const float*)d_in[6];
    const float* w_out    = (const float*)d_in[7];
    const float* b_out    = (const float*)d_in[8];
    float* out = (float*)d_out;

    float *vom, *smp, *bcat, *bp1, *bp2;
    cudaGetSymbolAddress((void**)&vom,  g_vom);
    cudaGetSymbolAddress((void**)&smp,  g_smp);
    cudaGetSymbolAddress((void**)&bcat, g_bcat);
    cudaGetSymbolAddress((void**)&bp1,  g_bp1);
    cudaGetSymbolAddress((void**)&bp2,  g_bp2);

    cudaFuncSetAttribute(gemm_mma<1>, cudaFuncAttributeMaxDynamicSharedMemorySize,
                         GEMM_SMEM_BYTES);
    cudaFuncSetAttribute(gemm_mma<0>, cudaFuncAttributeMaxDynamicSharedMemorySize,
                         GEMM_SMEM_BYTES);

    int pack_elems = NCAT * KDIM + CHN * KDIM + NCAT;
    pack_weights<<<(pack_elems + 255) / 256, 256>>>(w_value, b_value, w_offset,
                                                    b_offset, w_mask, b_mask, w_out);

    // GEMM-1: x(32768,256) @ [wv|wo|wm](256,384) + bcat -> vom (ldc=384); rounds A
    gemm_mma<1><<<dim3(NCAT / 128, MROWS / 128), 256, GEMM_SMEM_BYTES>>>(x, bp1, bcat,
                                                                         vom, NCAT);

    // DCNv4 sampling -> smp(32768,256), tf32-rounded on store
    dcn_sample<<<MROWS / 4, 256>>>(vom, smp);

    // GEMM-2: smp(32768,256) @ w_out(256,256) + b_out -> out (ldc=256)
    gemm_mma<0><<<dim3(CHN / 128, MROWS / 128), 256, GEMM_SMEM_BYTES>>>(smp, bp2, b_out,
                                                                        out, CHN);
}

// round 6
// speedup vs baseline: 3.2752x; 1.0460x over previous
#include <cuda_runtime.h>
#include <cstdint>

#define NB   8
#define HH   64
#define WWD  64
#define LQ   4096
#define CHN  256
#define NCAT 384
#define MROWS (NB * LQ)           // 32768
#define KDIM 256
#define PADK 36                   // smem row stride (floats)
#define BUF_A (256 * PADK)        // 9216 floats per A stage (256 rows)
#define BUF_B (128 * PADK)        // 4608 floats per B stage (128 n-rows)
#define GEMM_SMEM_BYTES ((2 * BUF_A + 2 * BUF_B) * 4)   // 110592 B

// ---- scratch (device globals; no allocation allowed) ----
__device__ float g_bcat[NCAT];
__device__ float g_vom[(size_t)MROWS * NCAT];
__device__ float g_smp[(size_t)MROWS * CHN];
__device__ float g_bp1[NCAT * KDIM];   // GEMM-1 B, col-major [n][k], tf32-rounded
__device__ float g_bp2[CHN * KDIM];    // GEMM-2 B, col-major [n][k], tf32-rounded

__device__ __forceinline__ float tf32r(float x) {
    asm("cvt.rna.tf32.f32 %0, %0;" : "+f"(x));
    return x;
}
__device__ __forceinline__ void cpasync16(uint32_t dst, const float* src) {
    asm volatile("cp.async.ca.shared.global [%0], [%1], 16;"
                 :: "r"(dst), "l"(src));
}

// ---------------------------------------------------------------------------
// Pack weights (col-major, tf32-rounded) + concat biases.
// ---------------------------------------------------------------------------
__global__ void pack_weights(const float* __restrict__ wv, const float* __restrict__ bv,
                             const float* __restrict__ wo, const float* __restrict__ bo,
                             const float* __restrict__ wm, const float* __restrict__ bm,
                             const float* __restrict__ wout)
{
    int idx = blockIdx.x * 256 + threadIdx.x;
    if (idx < NCAT * KDIM) {
        int n = idx >> 8, k = idx & 255;
        float val = 0.f;
        if (n < 256)      val = wv[k * 256 + n];
        else if (n < 328) val = wo[k * 72 + (n - 256)];
        else if (n < 364) val = wm[k * 36 + (n - 328)];
        g_bp1[idx] = tf32r(val);
    } else if (idx < NCAT * KDIM + CHN * KDIM) {
        int j = idx - NCAT * KDIM;
        int n = j >> 8, k = j & 255;
        g_bp2[j] = tf32r(wout[k * 256 + n]);
    } else if (idx < NCAT * KDIM + CHN * KDIM + NCAT) {
        int c = idx - (NCAT * KDIM + CHN * KDIM);
        float val = 0.f;
        if (c < 256)      val = bv[c];
        else if (c < 328) val = bo[c - 256];
        else if (c < 364) val = bm[c - 328];
        g_bcat[c] = val;
    }
}

// ---------------------------------------------------------------------------
// tf32 mma.sync GEMM, cp.async double-buffered, ONE sync per K-chunk.
// C(M,N) = A(M,256) @ B^T + bias. B col-major pre-rounded.
// ROUND_A=1: tf32-round A fragments after LDS (raw fp32 A input).
// CTA tile 256x128, 8 warps (4m x 2n), warp tile 64x64, BK=32.
// ---------------------------------------------------------------------------
template<int ROUND_A>
__global__ __launch_bounds__(256) void gemm_mma(const float* __restrict__ A,
                                                const float* __restrict__ Bcm,
                                                const float* __restrict__ bias,
                                                float* __restrict__ C, int ldc)
{
    extern __shared__ float smem[];
    uint32_t sbase = (uint32_t)__cvta_generic_to_shared(smem);

    int tid = threadIdx.x;
    int warp = tid >> 5, lane = tid & 31;
    int wmi = warp >> 1;          // 0..3 (M, 64-row tiles)
    int wni = warp & 1;           // 0..1 (N, 64-col tiles)
    int gid = lane >> 2, tg = lane & 3;

    const float* Ab = A   + (size_t)blockIdx.y * 256 * KDIM;
    const float* Bb = Bcm + (size_t)blockIdx.x * 128 * KDIM;

    int r0 = tid >> 3, q0 = (tid & 7) * 4;   // slot base: row r0 (+32 per j), quad q0

    float acc[4][8][4];
#pragma unroll
    for (int mt = 0; mt < 4; ++mt)
#pragma unroll
        for (int nt = 0; nt < 8; ++nt)
#pragma unroll
            for (int i = 0; i < 4; ++i) acc[mt][nt][i] = 0.f;

    auto issue = [&](int c, int b) {
        uint32_t adst = sbase + (uint32_t)(b * BUF_A) * 4;
        uint32_t bdst = sbase + (uint32_t)(2 * BUF_A + b * BUF_B) * 4;
        const float* asrc = Ab + c * 32;
        const float* bsrc = Bb + c * 32;
#pragma unroll
        for (int j = 0; j < 8; ++j) {        // A: 256 rows x 32 k
            int r = r0 + j * 32;
            cpasync16(adst + (uint32_t)(r * PADK + q0) * 4, asrc + (size_t)r * KDIM + q0);
        }
#pragma unroll
        for (int j = 0; j < 4; ++j) {        // B: 128 n x 32 k
            int r = r0 + j * 32;
            cpasync16(bdst + (uint32_t)(r * PADK + q0) * 4, bsrc + (size_t)r * KDIM + q0);
        }
        asm volatile("cp.async.commit_group;" ::: "memory");
    };

    issue(0, 0);

    for (int c = 0; c < 8; ++c) {
        int b = c & 1;
        asm volatile("cp.async.wait_group 0;" ::: "memory");
        __syncthreads();                      // tile c ready AND all warps done with c-1
        if (c < 7) issue(c + 1, b ^ 1);       // overwrites buffer of c-1 (safe), overlaps compute

        const float* As = smem + b * BUF_A;
        const float* Bs = smem + 2 * BUF_A + b * BUF_B;
#pragma unroll
        for (int ks = 0; ks < 4; ++ks) {
            int kb = ks * 8;
            uint32_t a[4][4], bf[8][2];
#pragma unroll
            for (int mt = 0; mt < 4; ++mt) {
                int row = wmi * 64 + mt * 16;
                float a0 = As[(row + gid) * PADK + kb + tg];
                float a1 = As[(row + gid + 8) * PADK + kb + tg];
                float a2 = As[(row + gid) * PADK + kb + tg + 4];
                float a3 = As[(row + gid + 8) * PADK + kb + tg + 4];
                if (ROUND_A) { a0 = tf32r(a0); a1 = tf32r(a1); a2 = tf32r(a2); a3 = tf32r(a3); }
                a[mt][0] = __float_as_uint(a0);
                a[mt][1] = __float_as_uint(a1);
                a[mt][2] = __float_as_uint(a2);
                a[mt][3] = __float_as_uint(a3);
            }
#pragma unroll
            for (int nt = 0; nt < 8; ++nt) {
                int n = wni * 64 + nt * 8 + gid;
                bf[nt][0] = __float_as_uint(Bs[n * PADK + kb + tg]);
                bf[nt][1] = __float_as_uint(Bs[n * PADK + kb + tg + 4]);
            }
#pragma unroll
            for (int mt = 0; mt < 4; ++mt)
#pragma unroll
                for (int nt = 0; nt < 8; ++nt) {
                    asm volatile(
                        "mma.sync.aligned.m16n8k8.row.col.f32.tf32.tf32.f32 "
                        "{%0,%1,%2,%3}, {%4,%5,%6,%7}, {%8,%9}, {%0,%1,%2,%3};"
                        : "+f"(acc[mt][nt][0]), "+f"(acc[mt][nt][1]),
                          "+f"(acc[mt][nt][2]), "+f"(acc[mt][nt][3])
                        : "r"(a[mt][0]), "r"(a[mt][1]), "r"(a[mt][2]), "r"(a[mt][3]),
                          "r"(bf[nt][0]), "r"(bf[nt][1]));
                }
        }
    }

#pragma unroll
    for (int mt = 0; mt < 4; ++mt) {
#pragma unroll
        for (int i = 0; i < 2; ++i) {
            size_t row = (size_t)blockIdx.y * 256 + wmi * 64 + mt * 16 + gid + i * 8;
            float* Crow = C + row * (size_t)ldc;
#pragma unroll
            for (int nt = 0; nt < 8; ++nt) {
                int col = blockIdx.x * 128 + wni * 64 + nt * 8 + 2 * tg;
                float2 o;
                o.x = acc[mt][nt][2 * i + 0] + bias[col + 0];
                o.y = acc[mt][nt][2 * i + 1] + bias[col + 1];
                *(float2*)(&Crow[col]) = o;
            }
        }
    }
}

// ---------------------------------------------------------------------------
// DCNv4 bilinear sampling (unchanged from R5). 4 queries per 256-thread block.
// ---------------------------------------------------------------------------
__global__ __launch_bounds__(256) void dcn_sample(const float* __restrict__ vom,
                                                  float* __restrict__ smp)
{
    int tid = threadIdx.x;
    int qbase = blockIdx.x * 4;

    __shared__ float4 s_wgt[4][4][9];
    __shared__ int4   s_idx[4][4][9];

    if (tid < 144) {
        int qq = tid / 36, u = tid % 36;
        int g = u / 9, p = u % 9;
        int q = qbase + qq;
        int hw = q & 4095, h = hw >> 6, w = hw & 63;
        const float* row = vom + (size_t)q * NCAT;
        float ox = row[256 + g * 18 + p * 2];
        float oy = row[256 + g * 18 + p * 2 + 1];
        float m  = row[328 + g * 9 + p];

        int ix = p / 3, iy = p % 3;
        float gx = (float)(w + ix - 1) + ox;
        float gy = (float)(h + iy - 1) + oy;

        float x0f = floorf(gx), y0f = floorf(gy);
        int x0 = (int)x0f, y0 = (int)y0f;
        float wx = gx - x0f, wy = gy - y0f;

        float vx0 = (x0 >= 0 && x0 < WWD) ? 1.f : 0.f;
        float vx1 = (x0 + 1 >= 0 && x0 + 1 < WWD) ? 1.f : 0.f;
        float vy0 = (y0 >= 0 && y0 < HH) ? 1.f : 0.f;
        float vy1 = (y0 + 1 >= 0 && y0 + 1 < HH) ? 1.f : 0.f;

        float4 W;
        W.x = (1.f - wx) * (1.f - wy) * m * vx0 * vy0;
        W.y = wx * (1.f - wy) * m * vx1 * vy0;
        W.z = (1.f - wx) * wy * m * vx0 * vy1;
        W.w = wx * wy * m * vx1 * vy1;

        int x0c = min(max(x0, 0), WWD - 1);
        int x1c = min(max(x0 + 1, 0), WWD - 1);
        int y0c = min(max(y0, 0), HH - 1);
        int y1c = min(max(y0 + 1, 0), HH - 1);

        int4 O;
        O.x = (y0c * WWD + x0c) * (NCAT * 4);
        O.y = (y0c * WWD + x1c) * (NCAT * 4);
        O.z = (y1c * WWD + x0c) * (NCAT * 4);
        O.w = (y1c * WWD + x1c) * (NCAT * 4);

        s_wgt[qq][g][p] = W;
        s_idx[qq][g][p] = O;
    }
    __syncthreads();

    int qi = tid >> 6;
    int s  = tid & 63;
    int g  = s >> 4;
    int c4 = s & 15;
    int q = qbase + qi;
    int n = q >> 12;

    const char* vb = (const char*)(vom + (size_t)(n * LQ) * NCAT + g * 64 + c4 * 4);

    float4 acc = make_float4(0.f, 0.f, 0.f, 0.f);
#pragma unroll
    for (int p = 0; p < 9; ++p) {
        float4 W = s_wgt[qi][g][p];
        int4   O = s_idx[qi][g][p];

        float4 v00 = *(const float4*)(vb + O.x);
        float4 v10 = *(const float4*)(vb + O.y);
        float4 v01 = *(const float4*)(vb + O.z);
        float4 v11 = *(const float4*)(vb + O.w);

        acc.x = fmaf(W.x, v00.x, acc.x); acc.y = fmaf(W.x, v00.y, acc.y);
        acc.z = fmaf(W.x, v00.z, acc.z); acc.w = fmaf(W.x, v00.w, acc.w);
        acc.x = fmaf(W.y, v10.x, acc.x); acc.y = fmaf(W.y, v10.y, acc.y);
        acc.z = fmaf(W.y, v10.z, acc.z); acc.w = fmaf(W.y, v10.w, acc.w);
        acc.x = fmaf(W.z, v01.x, acc.x); acc.y = fmaf(W.z, v01.y, acc.y);
        acc.z = fmaf(W.z, v01.z, acc.z); acc.w = fmaf(W.z, v01.w, acc.w);
        acc.x = fmaf(W.w, v11.x, acc.x); acc.y = fmaf(W.w, v11.y, acc.y);
        acc.z = fmaf(W.w, v11.z, acc.z); acc.w = fmaf(W.w, v11.w, acc.w);
    }

    acc.x = tf32r(acc.x); acc.y = tf32r(acc.y);
    acc.z = tf32r(acc.z); acc.w = tf32r(acc.w);
    *(float4*)(smp + (size_t)q * CHN + g * 64 + c4 * 4) = acc;
}

// ---------------------------------------------------------------------------
extern "C" void kernel_launch(void* const* d_in, const int* in_sizes, int n_in,
                              void* d_out, int out_size)
{
    const float* x        = (const float*)d_in[0];
    const float* w_value  = (const float*)d_in[1];
    const float* b_value  = (const float*)d_in[2];
    const float* w_offset = (const float*)d_in[3];
    const float* b_offset = (const float*)d_in[4];
    const float* w_mask   = (const float*)d_in[5];
    const float* b_mask   = (const float*)d_in[6];
    const float* w_out    = (const float*)d_in[7];
    const float* b_out    = (const float*)d_in[8];
    float* out = (float*)d_out;

    float *vom, *smp, *bcat, *bp1, *bp2;
    cudaGetSymbolAddress((void**)&vom,  g_vom);
    cudaGetSymbolAddress((void**)&smp,  g_smp);
    cudaGetSymbolAddress((void**)&bcat, g_bcat);
    cudaGetSymbolAddress((void**)&bp1,  g_bp1);
    cudaGetSymbolAddress((void**)&bp2,  g_bp2);

    cudaFuncSetAttribute(gemm_mma<1>, cudaFuncAttributeMaxDynamicSharedMemorySize,
                         GEMM_SMEM_BYTES);
    cudaFuncSetAttribute(gemm_mma<0>, cudaFuncAttributeMaxDynamicSharedMemorySize,
                         GEMM_SMEM_BYTES);

    int pack_elems = NCAT * KDIM + CHN * KDIM + NCAT;
    pack_weights<<<(pack_elems + 255) / 256, 256>>>(w_value, b_value, w_offset,
                                                    b_offset, w_mask, b_mask, w_out);

    // GEMM-1: x(32768,256) @ [wv|wo|wm](256,384) + bcat -> vom (ldc=384); rounds A
    gemm_mma<1><<<dim3(NCAT / 128, MROWS / 256), 256, GEMM_SMEM_BYTES>>>(x, bp1, bcat,
                                                                         vom, NCAT);

    // DCNv4 sampling -> smp(32768,256), tf32-rounded on store
    dcn_sample<<<MROWS / 4, 256>>>(vom, smp);

    // GEMM-2: smp(32768,256) @ w_out(256,256) + b_out -> out (ldc=256)
    gemm_mma<0><<<dim3(CHN / 128, MROWS / 256), 256, GEMM_SMEM_BYTES>>>(smp, bp2, b_out,
                                                                        out, CHN);
}